// round 9
// baseline (speedup 1.0000x reference)
#include <cuda_runtime.h>
#include <cuda_fp16.h>
#include <cstdint>

// x: [T=64, B=256, F_in=1024] fp32 -> A [M=16384, K=1024]
// W: [F_out=1024, F_in=1024] fp32  -> B [N=1024,  K=1024]
// cur = A @ B^T ; LIF scan over T -> spikes [T, B, F_out] fp32
//
// Approximate-then-repair (validated R6-R8, rel_err 0.0):
//   1) fp16x2 3-pass tensor GEMM (a0b0+a0b1+a1b0), error ~5e-6 rms.
//   2) LIF scan flags neurons with |h-1| < 1.5e-4 (~1.5k of 262k).
//   3) fixup recomputes flagged neurons with the EXACT ascending-k fp32 fmaf
//      chain (bitwise == reference) and reruns their scans.
// R9: GEMM retiled 128x64 @ 2 CTAs/SM so LDSM/barrier bubbles of one CTA
// overlap the MMA bursts of the other (tensor util 55% -> target ~80%).

#define T_STEPS 64
#define BATCH   256
#define K_DIM   1024
#define N_DIM   1024
#define M_DIM   (T_STEPS * BATCH)      // 16384
#define S_NEUR  (BATCH * N_DIM)        // 262144
#define MAXF    65536
#define FLAG_EPS 1.5e-4f

__device__ float   g_cur[(size_t)M_DIM * N_DIM];        // 64 MB
__device__ __half  g_Asp[(size_t)2 * M_DIM * K_DIM];    // 64 MB
__device__ __half  g_Bsp[(size_t)2 * N_DIM * K_DIM];    // 4 MB
__device__ int     g_flags[MAXF];
__device__ int     g_flagcnt;

// ---------------- helpers ----------------
__device__ __forceinline__ uint32_t smem_u32(const void* p) {
    uint32_t a;
    asm("{ .reg .u64 t; cvta.to.shared.u64 t, %1; cvt.u32.u64 %0, t; }"
        : "=r"(a) : "l"(p));
    return a;
}
__device__ __forceinline__ void cp_async16(uint32_t dst, const void* src) {
    asm volatile("cp.async.cg.shared.global [%0], [%1], 16;" :: "r"(dst), "l"(src));
}
#define CP_COMMIT() asm volatile("cp.async.commit_group;" ::: "memory")
#define CP_WAIT0()  asm volatile("cp.async.wait_group 0;" ::: "memory")
#define CP_WAIT1()  asm volatile("cp.async.wait_group 1;" ::: "memory")
#define CP_WAIT2()  asm volatile("cp.async.wait_group 2;" ::: "memory")

__device__ __forceinline__ void ldmx4(uint32_t* r, uint32_t addr) {
    asm volatile("ldmatrix.sync.aligned.m8n8.x4.shared.b16 {%0,%1,%2,%3}, [%4];"
                 : "=r"(r[0]), "=r"(r[1]), "=r"(r[2]), "=r"(r[3]) : "r"(addr));
}
__device__ __forceinline__ void mma16816(float* c, const uint32_t* a, const uint32_t* b) {
    asm volatile(
        "mma.sync.aligned.m16n8k16.row.col.f32.f16.f16.f32 "
        "{%0,%1,%2,%3}, {%4,%5,%6,%7}, {%8,%9}, {%0,%1,%2,%3};"
        : "+f"(c[0]), "+f"(c[1]), "+f"(c[2]), "+f"(c[3])
        : "r"(a[0]), "r"(a[1]), "r"(a[2]), "r"(a[3]), "r"(b[0]), "r"(b[1]));
}

// ---------------- split2 precompute (fp16 two-way split) ----------------
#define SPLIT_A_BLOCKS ((M_DIM * K_DIM) / 4 / 256)   // 16384
#define SPLIT_B_BLOCKS ((N_DIM * K_DIM) / 4 / 256)   // 1024

__global__ __launch_bounds__(256)
void split2_fused(const float* __restrict__ inA, __half* __restrict__ outA,
                  const float* __restrict__ inB, __half* __restrict__ outB)
{
    if (blockIdx.x == 0 && threadIdx.x == 0) g_flagcnt = 0;
    const float* in;
    __half* out;
    size_t n, idx;
    if (blockIdx.x < SPLIT_A_BLOCKS) {
        in = inA; out = outA; n = (size_t)M_DIM * K_DIM;
        idx = ((size_t)blockIdx.x * 256 + threadIdx.x) * 4;
    } else {
        in = inB; out = outB; n = (size_t)N_DIM * K_DIM;
        idx = ((size_t)(blockIdx.x - SPLIT_A_BLOCKS) * 256 + threadIdx.x) * 4;
    }
    float4 v = *(const float4*)(in + idx);
    __half h0[4], h1[4];
    h0[0] = __float2half_rn(v.x); h1[0] = __float2half_rn(v.x - __half2float(h0[0]));
    h0[1] = __float2half_rn(v.y); h1[1] = __float2half_rn(v.y - __half2float(h0[1]));
    h0[2] = __float2half_rn(v.z); h1[2] = __float2half_rn(v.z - __half2float(h0[2]));
    h0[3] = __float2half_rn(v.w); h1[3] = __float2half_rn(v.w - __half2float(h0[3]));
    __half2* o0 = (__half2*)(out + idx);
    __half2* o1 = (__half2*)(out + n + idx);
    o0[0] = __halves2half2(h0[0], h0[1]);  o0[1] = __halves2half2(h0[2], h0[3]);
    o1[0] = __halves2half2(h1[0], h1[1]);  o1[1] = __halves2half2(h1[2], h1[3]);
}

// ---------------- fp16x2 3-pass GEMM, 128x64 tile, 3 stages, 2 CTAs/SM ----------------
#define BM 128
#define BN 64
#define BK 32
#define NCHUNK (K_DIM / BK)            // 32
#define ROWB 80                        // 64B data + 16B pad
#define A_PLANE_B (128 * ROWB)         // 10240
#define B_PLANE_B (64 * ROWB)          // 5120
#define STAGE_B (2 * A_PLANE_B + 2 * B_PLANE_B)   // 30720
#define NSTAGE 3
#define SMEM_TOTAL (NSTAGE * STAGE_B)  // 92160

__device__ __forceinline__ uint32_t aplane_off(int stage, int plane) {
    return stage * STAGE_B + plane * A_PLANE_B;
}
__device__ __forceinline__ uint32_t bplane_off(int stage, int plane) {
    return stage * STAGE_B + 2 * A_PLANE_B + plane * B_PLANE_B;
}

__global__ __launch_bounds__(256, 2)
void gemm_fp16x2(const __half* __restrict__ Asp,
                 const __half* __restrict__ Bsp,
                 float* __restrict__ C)
{
    extern __shared__ char smem[];
    const uint32_t sb = smem_u32(smem);
    const int tid = threadIdx.x;
    const int wid = tid >> 5;
    const int lid = tid & 31;
    const int warp_m = wid & 3;        // 4 warps x 32 rows
    const int warp_n = wid >> 2;       // 2 warps x 32 cols

    const int rowBase = blockIdx.y * BM;
    const int colBase = blockIdx.x * BN;

    // per chunk: A 1024 segs + B 512 segs = 1536 x 16B -> 6 cp.async / thread
    auto load_chunk = [&](int kc, int stage) {
        const int k0 = kc * BK;
#pragma unroll
        for (int it = 0; it < 6; it++) {
            const int g = it * 256 + tid;
            if (g < 1024) {
                const int plane = g >> 9;
                const int row   = (g & 511) >> 2;
                const int seg   = g & 3;
                cp_async16(sb + aplane_off(stage, plane) + row * ROWB + seg * 16,
                           Asp + ((size_t)plane * M_DIM + rowBase + row) * K_DIM + k0 + seg * 8);
            } else {
                const int g2    = g - 1024;
                const int plane = g2 >> 8;
                const int row   = (g2 & 255) >> 2;
                const int seg   = g2 & 3;
                cp_async16(sb + bplane_off(stage, plane) + row * ROWB + seg * 16,
                           Bsp + ((size_t)plane * N_DIM + colBase + row) * K_DIM + k0 + seg * 8);
            }
        }
    };

    const int a_row = (lid & 15);
    const int a_ko  = (lid >> 4) * 8;
    const int b_row = (lid & 7) + ((lid >> 4) & 1) * 8;
    const int b_ko  = ((lid >> 3) & 1) * 8;

    float acc[2][4][4];                 // [mt][nt][4] = 32 regs
#pragma unroll
    for (int mt = 0; mt < 2; mt++)
#pragma unroll
        for (int nt = 0; nt < 4; nt++)
#pragma unroll
            for (int q = 0; q < 4; q++) acc[mt][nt][q] = 0.0f;

    load_chunk(0, 0);  CP_COMMIT();
    load_chunk(1, 1);  CP_COMMIT();
    load_chunk(2, 2);  CP_COMMIT();

    for (int i = 0; i < NCHUNK; i++) {
        const int s = i % NSTAGE;
        const int rem = NCHUNK - 1 - i;
        if (rem >= 2)      { CP_WAIT2(); }
        else if (rem == 1) { CP_WAIT1(); }
        else               { CP_WAIT0(); }
        __syncthreads();

        // ---- fragments for this chunk -> registers ----
        uint32_t af[2][2][2][4];   // [ks][plane][mt][4]  = 32 regs
        uint32_t bf[2][2][4][2];   // [ks][plane][nt][2]  = 32 regs
#pragma unroll
        for (int ks = 0; ks < 2; ks++) {
            const int kbyte = ks * 32;
#pragma unroll
            for (int p = 0; p < 2; p++) {
#pragma unroll
                for (int mt = 0; mt < 2; mt++) {
                    uint32_t addr = sb + aplane_off(s, p)
                                  + (warp_m * 32 + mt * 16 + a_row) * ROWB
                                  + kbyte + a_ko * 2;
                    ldmx4(af[ks][p][mt], addr);
                }
#pragma unroll
                for (int ng = 0; ng < 2; ng++) {
                    uint32_t r[4];
                    uint32_t addr = sb + bplane_off(s, p)
                                  + (warp_n * 32 + ng * 16 + b_row) * ROWB
                                  + kbyte + b_ko * 2;
                    ldmx4(r, addr);
                    bf[ks][p][ng * 2 + 0][0] = r[0]; bf[ks][p][ng * 2 + 0][1] = r[1];
                    bf[ks][p][ng * 2 + 1][0] = r[2]; bf[ks][p][ng * 2 + 1][1] = r[3];
                }
            }
        }

        // next chunk's loads overlap with the MMA burst
        if (i + 3 < NCHUNK) {
            load_chunk(i + 3, (i + 3) % NSTAGE);
            CP_COMMIT();
        }

        // ---- 3 passes x 2 ks x 8 tiles = 48 MMAs ----
#pragma unroll
        for (int ks = 0; ks < 2; ks++) {
#pragma unroll
            for (int p = 0; p < 3; p++) {
                const int pa = (p == 2) ? 1 : 0;   // (0,0) (0,1) (1,0)
                const int pb = (p == 1) ? 1 : 0;
#pragma unroll
                for (int mt = 0; mt < 2; mt++)
#pragma unroll
                    for (int nt = 0; nt < 4; nt++)
                        mma16816(acc[mt][nt], af[ks][pa][mt], bf[ks][pb][nt]);
            }
        }
    }

#pragma unroll
    for (int mt = 0; mt < 2; mt++) {
        const int r0 = rowBase + warp_m * 32 + mt * 16 + (lid >> 2);
        const int c0 = colBase + warp_n * 32 + (lid & 3) * 2;
#pragma unroll
        for (int nt = 0; nt < 4; nt++) {
            float* d0 = C + (size_t)r0 * N_DIM + c0 + nt * 8;
            float* d1 = C + (size_t)(r0 + 8) * N_DIM + c0 + nt * 8;
            *(float2*)d0 = make_float2(acc[mt][nt][0], acc[mt][nt][1]);
            *(float2*)d1 = make_float2(acc[mt][nt][2], acc[mt][nt][3]);
        }
    }
}

// ---------------- LIF scan + borderline flagging ----------------
__global__ __launch_bounds__(256)
void lif_flag_kernel(const float* __restrict__ cur, float* __restrict__ out)
{
    const int idx = blockIdx.x * blockDim.x + threadIdx.x;
    float v = 0.0f;
    bool flagged = false;
#pragma unroll
    for (int t = 0; t < T_STEPS; t++) {
        const float x = cur[(size_t)t * S_NEUR + idx];
        const float h = v + (x - v) * 0.5f;
        flagged |= (fabsf(h - 1.0f) < FLAG_EPS);
        const float sp = (h - 1.0f >= 0.0f) ? 1.0f : 0.0f;
        v = (sp != 0.0f) ? 0.0f : h;
        out[(size_t)t * S_NEUR + idx] = sp;
    }
    if (flagged) {
        int p = atomicAdd(&g_flagcnt, 1);
        if (p < MAXF) g_flags[p] = idx;
    }
}

// ---------------- exact fixup: 2 neurons / 128-thread block ----------------
__global__ __launch_bounds__(128)
void fixup_kernel(const float* __restrict__ x, const float* __restrict__ W,
                  float* __restrict__ out)
{
    __shared__ float Wrow[2][K_DIM];
    __shared__ float curex[2][T_STEPS];
    const int count = min(g_flagcnt, MAXF);
    const int sub  = threadIdx.x >> 6;
    const int st   = threadIdx.x & 63;

    for (int base = blockIdx.x * 2; base < count; base += gridDim.x * 2) {
        const int i = base + sub;
        const bool active = (i < count);
        int neuron = 0, b = 0, f = 0;
        if (active) {
            neuron = g_flags[i];
            b = neuron >> 10;
            f = neuron & 1023;
        }
        {
            const float4* wsrc = (const float4*)(W + (size_t)f * K_DIM);
            for (int j = st; j < K_DIM / 4; j += 64)
                ((float4*)Wrow[sub])[j] = wsrc[j];
        }
        __syncthreads();

        if (active) {
            const float4* xr = (const float4*)(x + ((size_t)st * BATCH + b) * K_DIM);
            float acc = 0.0f;
#pragma unroll 4
            for (int kb = 0; kb < K_DIM / 32; kb++) {
                float4 r[8];
#pragma unroll
                for (int q = 0; q < 8; q++) r[q] = xr[kb * 8 + q];
                const float* w = &Wrow[sub][kb * 32];
#pragma unroll
                for (int q = 0; q < 8; q++) {
                    acc = fmaf(r[q].x, w[q * 4 + 0], acc);
                    acc = fmaf(r[q].y, w[q * 4 + 1], acc);
                    acc = fmaf(r[q].z, w[q * 4 + 2], acc);
                    acc = fmaf(r[q].w, w[q * 4 + 3], acc);
                }
            }
            curex[sub][st] = acc;
        }
        __syncthreads();

        if (active && st == 0) {
            float v = 0.0f;
#pragma unroll
            for (int tt = 0; tt < T_STEPS; tt++) {
                const float h = v + (curex[sub][tt] - v) * 0.5f;
                const float sp = (h - 1.0f >= 0.0f) ? 1.0f : 0.0f;
                v = (sp != 0.0f) ? 0.0f : h;
                out[(size_t)tt * S_NEUR + neuron] = sp;
            }
        }
        __syncthreads();
    }
}

// Dummies keep ncu capture (offset-2) on the GEMM:
// pattern [split, d, d, gemm, lif, fixup].
__global__ void align_dummy() {}

// ---------------- launch ----------------
extern "C" void kernel_launch(void* const* d_in, const int* in_sizes, int n_in,
                              void* d_out, int out_size)
{
    (void)in_sizes; (void)n_in; (void)out_size;
    const float* x = (const float*)d_in[0];
    const float* W = (const float*)d_in[1];
    float* out = (float*)d_out;

    float* cur;    cudaGetSymbolAddress((void**)&cur,  g_cur);
    __half* Asp;   cudaGetSymbolAddress((void**)&Asp,  g_Asp);
    __half* Bsp;   cudaGetSymbolAddress((void**)&Bsp,  g_Bsp);

    cudaFuncSetAttribute(gemm_fp16x2,
                         cudaFuncAttributeMaxDynamicSharedMemorySize, SMEM_TOTAL);

    split2_fused<<<SPLIT_A_BLOCKS + SPLIT_B_BLOCKS, 256>>>(x, Asp, W, Bsp);

    align_dummy<<<1, 32>>>();
    align_dummy<<<1, 32>>>();

    dim3 grid(N_DIM / BN, M_DIM / BM);   // (16, 128) = 2048 CTAs
    gemm_fp16x2<<<grid, 256, SMEM_TOTAL>>>(Asp, Bsp, cur);

    lif_flag_kernel<<<S_NEUR / 256, 256>>>(cur, out);

    fixup_kernel<<<1024, 128>>>(x, W, out);
}

// round 10
// speedup vs baseline: 1.0949x; 1.0949x over previous
#include <cuda_runtime.h>
#include <cuda_fp16.h>
#include <cstdint>

// x: [T=64, B=256, F_in=1024] fp32 -> A [M=16384, K=1024]
// W: [F_out=1024, F_in=1024] fp32  -> B [N=1024,  K=1024]
// cur = A @ B^T ; LIF scan over T -> spikes [T, B, F_out] fp32
//
// Approximate-then-repair (validated R6-R9, rel_err 0.0):
//   1) fp16x2 3-pass tensor GEMM (a0b0+a0b1+a1b0), error ~5e-6 rms.
//   2) LIF scan flags neurons with |h-1| < 1.5e-4 (~1.5k of 262k).
//   3) fixup recomputes flagged neurons with the EXACT ascending-k fp32 fmaf
//      chain (bitwise == reference) and reruns their scans.
// R10: mainloop software-pipelined at k-slab granularity — fragment double
// buffering in registers, next slab's ldmatrix issued BEFORE current slab's
// MMA burst so LSU and tensor pipes overlap within each warp (fixes the
// phase-aligned LDSM/MMA serialization that capped tensor util at ~55%).

#define T_STEPS 64
#define BATCH   256
#define K_DIM   1024
#define N_DIM   1024
#define M_DIM   (T_STEPS * BATCH)      // 16384
#define S_NEUR  (BATCH * N_DIM)        // 262144
#define MAXF    65536
#define FLAG_EPS 1.5e-4f

__device__ float   g_cur[(size_t)M_DIM * N_DIM];        // 64 MB
__device__ __half  g_Asp[(size_t)2 * M_DIM * K_DIM];    // 64 MB
__device__ __half  g_Bsp[(size_t)2 * N_DIM * K_DIM];    // 4 MB
__device__ int     g_flags[MAXF];
__device__ int     g_flagcnt;

// ---------------- helpers ----------------
__device__ __forceinline__ uint32_t smem_u32(const void* p) {
    uint32_t a;
    asm("{ .reg .u64 t; cvta.to.shared.u64 t, %1; cvt.u32.u64 %0, t; }"
        : "=r"(a) : "l"(p));
    return a;
}
__device__ __forceinline__ void cp_async16(uint32_t dst, const void* src) {
    asm volatile("cp.async.cg.shared.global [%0], [%1], 16;" :: "r"(dst), "l"(src));
}
#define CP_COMMIT() asm volatile("cp.async.commit_group;" ::: "memory")
#define CP_WAIT0()  asm volatile("cp.async.wait_group 0;" ::: "memory")
#define CP_WAIT1()  asm volatile("cp.async.wait_group 1;" ::: "memory")
#define CP_WAIT2()  asm volatile("cp.async.wait_group 2;" ::: "memory")
#define CP_WAIT3()  asm volatile("cp.async.wait_group 3;" ::: "memory")

__device__ __forceinline__ void ldmx4(uint32_t* r, uint32_t addr) {
    asm volatile("ldmatrix.sync.aligned.m8n8.x4.shared.b16 {%0,%1,%2,%3}, [%4];"
                 : "=r"(r[0]), "=r"(r[1]), "=r"(r[2]), "=r"(r[3]) : "r"(addr));
}
__device__ __forceinline__ void mma16816(float* c, const uint32_t* a, const uint32_t* b) {
    asm volatile(
        "mma.sync.aligned.m16n8k16.row.col.f32.f16.f16.f32 "
        "{%0,%1,%2,%3}, {%4,%5,%6,%7}, {%8,%9}, {%0,%1,%2,%3};"
        : "+f"(c[0]), "+f"(c[1]), "+f"(c[2]), "+f"(c[3])
        : "r"(a[0]), "r"(a[1]), "r"(a[2]), "r"(a[3]), "r"(b[0]), "r"(b[1]));
}

// ---------------- split2 precompute (fp16 two-way split) ----------------
#define SPLIT_A_BLOCKS ((M_DIM * K_DIM) / 4 / 256)   // 16384
#define SPLIT_B_BLOCKS ((N_DIM * K_DIM) / 4 / 256)   // 1024

__global__ __launch_bounds__(256)
void split2_fused(const float* __restrict__ inA, __half* __restrict__ outA,
                  const float* __restrict__ inB, __half* __restrict__ outB)
{
    if (blockIdx.x == 0 && threadIdx.x == 0) g_flagcnt = 0;
    const float* in;
    __half* out;
    size_t n, idx;
    if (blockIdx.x < SPLIT_A_BLOCKS) {
        in = inA; out = outA; n = (size_t)M_DIM * K_DIM;
        idx = ((size_t)blockIdx.x * 256 + threadIdx.x) * 4;
    } else {
        in = inB; out = outB; n = (size_t)N_DIM * K_DIM;
        idx = ((size_t)(blockIdx.x - SPLIT_A_BLOCKS) * 256 + threadIdx.x) * 4;
    }
    float4 v = *(const float4*)(in + idx);
    __half h0[4], h1[4];
    h0[0] = __float2half_rn(v.x); h1[0] = __float2half_rn(v.x - __half2float(h0[0]));
    h0[1] = __float2half_rn(v.y); h1[1] = __float2half_rn(v.y - __half2float(h0[1]));
    h0[2] = __float2half_rn(v.z); h1[2] = __float2half_rn(v.z - __half2float(h0[2]));
    h0[3] = __float2half_rn(v.w); h1[3] = __float2half_rn(v.w - __half2float(h0[3]));
    __half2* o0 = (__half2*)(out + idx);
    __half2* o1 = (__half2*)(out + n + idx);
    o0[0] = __halves2half2(h0[0], h0[1]);  o0[1] = __halves2half2(h0[2], h0[3]);
    o1[0] = __halves2half2(h1[0], h1[1]);  o1[1] = __halves2half2(h1[2], h1[3]);
}

// ---------------- fp16x2 3-pass GEMM, 128x128x32, 5 stages, slab-pipelined ----------------
#define BM 128
#define BN 128
#define BK 32
#define NCHUNK (K_DIM / BK)            // 32
#define ROWB 80                        // 64B data + 16B pad (conflict-free)
#define PLANE_B (128 * ROWB)           // 10240
#define NPLANE 4                       // A0, A1, B0, B1
#define STAGE_B (NPLANE * PLANE_B)     // 40960
#define NSTAGE 5
#define SMEM_TOTAL (NSTAGE * STAGE_B)  // 204800

__device__ __forceinline__ uint32_t pl_off(int stage, int plane) {
    return stage * STAGE_B + plane * PLANE_B;
}

struct Frag {
    uint32_t af[2][2][4];   // [plane][mt][4]
    uint32_t bf[2][8][2];   // [plane][nt][2]
};

__global__ __launch_bounds__(256, 1)
void gemm_fp16x2(const __half* __restrict__ Asp,
                 const __half* __restrict__ Bsp,
                 float* __restrict__ C)
{
    extern __shared__ char smem[];
    const uint32_t sb = smem_u32(smem);
    const int tid = threadIdx.x;
    const int wid = tid >> 5;
    const int lid = tid & 31;
    const int warp_m = wid & 3;        // 4 warps along M (32 rows)
    const int warp_n = wid >> 2;       // 2 warps along N (64 cols)

    const int rowBase = blockIdx.y * BM;
    const int colBase = blockIdx.x * BN;

    auto load_chunk = [&](int kc, int stage) {
        const int k0 = kc * BK;
#pragma unroll
        for (int it = 0; it < 8; it++) {
            const int g     = it * 256 + tid;
            const int plane = g >> 9;            // 0..3
            const int row   = (g & 511) >> 2;
            const int seg   = g & 3;
            const __half* src = (plane < 2)
                ? Asp + ((size_t)plane * M_DIM + rowBase + row) * K_DIM + k0 + seg * 8
                : Bsp + ((size_t)(plane - 2) * N_DIM + colBase + row) * K_DIM + k0 + seg * 8;
            cp_async16(sb + pl_off(stage, plane) + row * ROWB + seg * 16, src);
        }
    };

    const int a_row = (lid & 15);
    const int a_ko  = (lid >> 4) * 8;
    const int b_row = (lid & 7) + ((lid >> 4) & 1) * 8;
    const int b_ko  = ((lid >> 3) & 1) * 8;

    // ldsm for one k-slab (ks = 0/1) of one stage into a fragment buffer
    auto ldsm_slab = [&](int s, int ks, Frag& fr) {
        const int kbyte = ks * 32;
#pragma unroll
        for (int p = 0; p < 2; p++) {
#pragma unroll
            for (int mt = 0; mt < 2; mt++) {
                uint32_t addr = sb + pl_off(s, p)
                              + (warp_m * 32 + mt * 16 + a_row) * ROWB
                              + kbyte + a_ko * 2;
                ldmx4(fr.af[p][mt], addr);
            }
#pragma unroll
            for (int ng = 0; ng < 4; ng++) {
                uint32_t r[4];
                uint32_t addr = sb + pl_off(s, 2 + p)
                              + (warp_n * 64 + ng * 16 + b_row) * ROWB
                              + kbyte + b_ko * 2;
                ldmx4(r, addr);
                fr.bf[p][ng * 2 + 0][0] = r[0]; fr.bf[p][ng * 2 + 0][1] = r[1];
                fr.bf[p][ng * 2 + 1][0] = r[2]; fr.bf[p][ng * 2 + 1][1] = r[3];
            }
        }
    };

    float acc[2][8][4];
#pragma unroll
    for (int mt = 0; mt < 2; mt++)
#pragma unroll
        for (int nt = 0; nt < 8; nt++)
#pragma unroll
            for (int q = 0; q < 4; q++) acc[mt][nt][q] = 0.0f;

    auto mma_slab = [&](const Frag& fr) {
#pragma unroll
        for (int p = 0; p < 3; p++) {
            const int pa = (p == 2) ? 1 : 0;   // passes: (0,0) (0,1) (1,0)
            const int pb = (p == 1) ? 1 : 0;
#pragma unroll
            for (int mt = 0; mt < 2; mt++)
#pragma unroll
                for (int nt = 0; nt < 8; nt++)
                    mma16816(acc[mt][nt], fr.af[pa][mt], fr.bf[pb][nt]);
        }
    };

    // prologue: 4 chunks in flight, stage 0 ready, slab (0, ks=0) in regs
    load_chunk(0, 0);  CP_COMMIT();
    load_chunk(1, 1);  CP_COMMIT();
    load_chunk(2, 2);  CP_COMMIT();
    load_chunk(3, 3);  CP_COMMIT();
    CP_WAIT3();
    __syncthreads();

    Frag frag[2];
    ldsm_slab(0, 0, frag[0]);

    for (int i = 0; i < NCHUNK; i++) {
        const int s = i % NSTAGE;

        // slab ks=0: prefetch ks=1 fragments, then MMA ks=0
        ldsm_slab(s, 1, frag[1]);
        mma_slab(frag[0]);

        // chunk boundary: commit chunk i+4, wait for chunk i+1, barrier,
        // prefetch next chunk's ks=0 fragments — all BEFORE the ks=1 MMAs.
        if (i + 1 < NCHUNK) {
            if (i + 4 < NCHUNK) {
                load_chunk(i + 4, (i + 4) % NSTAGE);
                CP_COMMIT();
            }
            const int rem = NCHUNK - 2 - i;   // chunks after i+1
            if (rem >= 3)      { CP_WAIT3(); }
            else if (rem == 2) { CP_WAIT2(); }
            else if (rem == 1) { CP_WAIT1(); }
            else               { CP_WAIT0(); }
            __syncthreads();
            ldsm_slab((i + 1) % NSTAGE, 0, frag[0]);
        }

        mma_slab(frag[1]);
    }

    // epilogue
#pragma unroll
    for (int mt = 0; mt < 2; mt++) {
        const int r0 = rowBase + warp_m * 32 + mt * 16 + (lid >> 2);
        const int c0 = colBase + warp_n * 64 + (lid & 3) * 2;
#pragma unroll
        for (int nt = 0; nt < 8; nt++) {
            float* d0 = C + (size_t)r0 * N_DIM + c0 + nt * 8;
            float* d1 = C + (size_t)(r0 + 8) * N_DIM + c0 + nt * 8;
            *(float2*)d0 = make_float2(acc[mt][nt][0], acc[mt][nt][1]);
            *(float2*)d1 = make_float2(acc[mt][nt][2], acc[mt][nt][3]);
        }
    }
}

// ---------------- LIF scan + borderline flagging ----------------
__global__ __launch_bounds__(256)
void lif_flag_kernel(const float* __restrict__ cur, float* __restrict__ out)
{
    const int idx = blockIdx.x * blockDim.x + threadIdx.x;
    float v = 0.0f;
    bool flagged = false;
#pragma unroll
    for (int t = 0; t < T_STEPS; t++) {
        const float x = cur[(size_t)t * S_NEUR + idx];
        const float h = v + (x - v) * 0.5f;
        flagged |= (fabsf(h - 1.0f) < FLAG_EPS);
        const float sp = (h - 1.0f >= 0.0f) ? 1.0f : 0.0f;
        v = (sp != 0.0f) ? 0.0f : h;
        out[(size_t)t * S_NEUR + idx] = sp;
    }
    if (flagged) {
        int p = atomicAdd(&g_flagcnt, 1);
        if (p < MAXF) g_flags[p] = idx;
    }
}

// ---------------- exact fixup: 2 neurons / 128-thread block ----------------
__global__ __launch_bounds__(128)
void fixup_kernel(const float* __restrict__ x, const float* __restrict__ W,
                  float* __restrict__ out)
{
    __shared__ float Wrow[2][K_DIM];
    __shared__ float curex[2][T_STEPS];
    const int count = min(g_flagcnt, MAXF);
    const int sub  = threadIdx.x >> 6;
    const int st   = threadIdx.x & 63;

    for (int base = blockIdx.x * 2; base < count; base += gridDim.x * 2) {
        const int i = base + sub;
        const bool active = (i < count);
        int neuron = 0, b = 0, f = 0;
        if (active) {
            neuron = g_flags[i];
            b = neuron >> 10;
            f = neuron & 1023;
        }
        {
            const float4* wsrc = (const float4*)(W + (size_t)f * K_DIM);
            for (int j = st; j < K_DIM / 4; j += 64)
                ((float4*)Wrow[sub])[j] = wsrc[j];
        }
        __syncthreads();

        if (active) {
            const float4* xr = (const float4*)(x + ((size_t)st * BATCH + b) * K_DIM);
            float acc = 0.0f;
#pragma unroll 4
            for (int kb = 0; kb < K_DIM / 32; kb++) {
                float4 r[8];
#pragma unroll
                for (int q = 0; q < 8; q++) r[q] = xr[kb * 8 + q];
                const float* w = &Wrow[sub][kb * 32];
#pragma unroll
                for (int q = 0; q < 8; q++) {
                    acc = fmaf(r[q].x, w[q * 4 + 0], acc);
                    acc = fmaf(r[q].y, w[q * 4 + 1], acc);
                    acc = fmaf(r[q].z, w[q * 4 + 2], acc);
                    acc = fmaf(r[q].w, w[q * 4 + 3], acc);
                }
            }
            curex[sub][st] = acc;
        }
        __syncthreads();

        if (active && st == 0) {
            float v = 0.0f;
#pragma unroll
            for (int tt = 0; tt < T_STEPS; tt++) {
                const float h = v + (curex[sub][tt] - v) * 0.5f;
                const float sp = (h - 1.0f >= 0.0f) ? 1.0f : 0.0f;
                v = (sp != 0.0f) ? 0.0f : h;
                out[(size_t)tt * S_NEUR + neuron] = sp;
            }
        }
        __syncthreads();
    }
}

// Dummies keep ncu capture (offset-2) on the GEMM:
// pattern [split, d, d, gemm, lif, fixup].
__global__ void align_dummy() {}

// ---------------- launch ----------------
extern "C" void kernel_launch(void* const* d_in, const int* in_sizes, int n_in,
                              void* d_out, int out_size)
{
    (void)in_sizes; (void)n_in; (void)out_size;
    const float* x = (const float*)d_in[0];
    const float* W = (const float*)d_in[1];
    float* out = (float*)d_out;

    float* cur;    cudaGetSymbolAddress((void**)&cur,  g_cur);
    __half* Asp;   cudaGetSymbolAddress((void**)&Asp,  g_Asp);
    __half* Bsp;   cudaGetSymbolAddress((void**)&Bsp,  g_Bsp);

    cudaFuncSetAttribute(gemm_fp16x2,
                         cudaFuncAttributeMaxDynamicSharedMemorySize, SMEM_TOTAL);

    split2_fused<<<SPLIT_A_BLOCKS + SPLIT_B_BLOCKS, 256>>>(x, Asp, W, Bsp);

    align_dummy<<<1, 32>>>();
    align_dummy<<<1, 32>>>();

    dim3 grid(N_DIM / BN, M_DIM / BM);   // (8, 128) = 1024 CTAs
    gemm_fp16x2<<<grid, 256, SMEM_TOTAL>>>(Asp, Bsp, cur);

    lif_flag_kernel<<<S_NEUR / 256, 256>>>(cur, out);

    fixup_kernel<<<1024, 128>>>(x, W, out);
}

// round 12
// speedup vs baseline: 1.1734x; 1.0718x over previous
#include <cuda_runtime.h>
#include <cuda_fp16.h>
#include <cstdint>

// x: [T=64, B=256, F_in=1024] fp32 -> A [M=16384, K=1024]
// W: [F_out=1024, F_in=1024] fp32  -> B [N=1024,  K=1024]
// cur = A @ B^T ; LIF scan over T -> spikes [T, B, F_out] fp32
//
// Approximate-then-repair (validated R6-R10, rel_err 0.0):
//   1) fp16x2 3-pass tensor GEMM (a0b0+a0b1+a1b0), error ~5e-6 rms.
//   2) LIF scan flags neurons with |h-1| < 1.5e-4 (~1.5k of 262k).
//   3) fixup recomputes flagged neurons with the EXACT ascending-k fp32 fmaf
//      chain (bitwise == reference) and reruns their scans.
// R12 = R11 (128x64 @ 2 CTAs/SM + slab double-buffering) with the stage-alias
// race FIXED: all writes to a smem stage are issued only after the barrier
// that proves every warp finished reading it (wait -> sync -> ldsm -> load).

#define T_STEPS 64
#define BATCH   256
#define K_DIM   1024
#define N_DIM   1024
#define M_DIM   (T_STEPS * BATCH)      // 16384
#define S_NEUR  (BATCH * N_DIM)        // 262144
#define MAXF    65536
#define FLAG_EPS 1.5e-4f

__device__ float   g_cur[(size_t)M_DIM * N_DIM];        // 64 MB
__device__ __half  g_Asp[(size_t)2 * M_DIM * K_DIM];    // 64 MB
__device__ __half  g_Bsp[(size_t)2 * N_DIM * K_DIM];    // 4 MB
__device__ int     g_flags[MAXF];
__device__ int     g_flagcnt;

// ---------------- helpers ----------------
__device__ __forceinline__ uint32_t smem_u32(const void* p) {
    uint32_t a;
    asm("{ .reg .u64 t; cvta.to.shared.u64 t, %1; cvt.u32.u64 %0, t; }"
        : "=r"(a) : "l"(p));
    return a;
}
__device__ __forceinline__ void cp_async16(uint32_t dst, const void* src) {
    asm volatile("cp.async.cg.shared.global [%0], [%1], 16;" :: "r"(dst), "l"(src));
}
#define CP_COMMIT() asm volatile("cp.async.commit_group;" ::: "memory")
#define CP_WAIT0()  asm volatile("cp.async.wait_group 0;" ::: "memory")
#define CP_WAIT1()  asm volatile("cp.async.wait_group 1;" ::: "memory")
#define CP_WAIT2()  asm volatile("cp.async.wait_group 2;" ::: "memory")

__device__ __forceinline__ void ldmx4(uint32_t* r, uint32_t addr) {
    asm volatile("ldmatrix.sync.aligned.m8n8.x4.shared.b16 {%0,%1,%2,%3}, [%4];"
                 : "=r"(r[0]), "=r"(r[1]), "=r"(r[2]), "=r"(r[3]) : "r"(addr));
}
__device__ __forceinline__ void mma16816(float* c, const uint32_t* a, const uint32_t* b) {
    asm volatile(
        "mma.sync.aligned.m16n8k16.row.col.f32.f16.f16.f32 "
        "{%0,%1,%2,%3}, {%4,%5,%6,%7}, {%8,%9}, {%0,%1,%2,%3};"
        : "+f"(c[0]), "+f"(c[1]), "+f"(c[2]), "+f"(c[3])
        : "r"(a[0]), "r"(a[1]), "r"(a[2]), "r"(a[3]), "r"(b[0]), "r"(b[1]));
}

// ---------------- split2 precompute (fp16 two-way split) ----------------
#define SPLIT_A_BLOCKS ((M_DIM * K_DIM) / 4 / 256)   // 16384
#define SPLIT_B_BLOCKS ((N_DIM * K_DIM) / 4 / 256)   // 1024

__global__ __launch_bounds__(256)
void split2_fused(const float* __restrict__ inA, __half* __restrict__ outA,
                  const float* __restrict__ inB, __half* __restrict__ outB)
{
    if (blockIdx.x == 0 && threadIdx.x == 0) g_flagcnt = 0;
    const float* in;
    __half* out;
    size_t n, idx;
    if (blockIdx.x < SPLIT_A_BLOCKS) {
        in = inA; out = outA; n = (size_t)M_DIM * K_DIM;
        idx = ((size_t)blockIdx.x * 256 + threadIdx.x) * 4;
    } else {
        in = inB; out = outB; n = (size_t)N_DIM * K_DIM;
        idx = ((size_t)(blockIdx.x - SPLIT_A_BLOCKS) * 256 + threadIdx.x) * 4;
    }
    float4 v = *(const float4*)(in + idx);
    __half h0[4], h1[4];
    h0[0] = __float2half_rn(v.x); h1[0] = __float2half_rn(v.x - __half2float(h0[0]));
    h0[1] = __float2half_rn(v.y); h1[1] = __float2half_rn(v.y - __half2float(h0[1]));
    h0[2] = __float2half_rn(v.z); h1[2] = __float2half_rn(v.z - __half2float(h0[2]));
    h0[3] = __float2half_rn(v.w); h1[3] = __float2half_rn(v.w - __half2float(h0[3]));
    __half2* o0 = (__half2*)(out + idx);
    __half2* o1 = (__half2*)(out + n + idx);
    o0[0] = __halves2half2(h0[0], h0[1]);  o0[1] = __halves2half2(h0[2], h0[3]);
    o1[0] = __halves2half2(h1[0], h1[1]);  o1[1] = __halves2half2(h1[2], h1[3]);
}

// ------- fp16x2 3-pass GEMM, 128x64 tile, 3 stages, 2 CTAs/SM, slab-pipelined -------
#define BM 128
#define BN 64
#define BK 32
#define NCHUNK (K_DIM / BK)            // 32
#define ROWB 80                        // 64B data + 16B pad
#define A_PLANE_B (128 * ROWB)         // 10240
#define B_PLANE_B (64 * ROWB)          // 5120
#define STAGE_B (2 * A_PLANE_B + 2 * B_PLANE_B)   // 30720
#define NSTAGE 3
#define SMEM_TOTAL (NSTAGE * STAGE_B)  // 92160 (x2 CTAs = 184320 <= 228KB)

__device__ __forceinline__ uint32_t aplane_off(int stage, int plane) {
    return stage * STAGE_B + plane * A_PLANE_B;
}
__device__ __forceinline__ uint32_t bplane_off(int stage, int plane) {
    return stage * STAGE_B + 2 * A_PLANE_B + plane * B_PLANE_B;
}

struct Frag {
    uint32_t af[2][2][4];   // [plane][mt][4]
    uint32_t bf[2][4][2];   // [plane][nt][2]
};

__global__ __launch_bounds__(256, 2)
void gemm_fp16x2(const __half* __restrict__ Asp,
                 const __half* __restrict__ Bsp,
                 float* __restrict__ C)
{
    extern __shared__ char smem[];
    const uint32_t sb = smem_u32(smem);
    const int tid = threadIdx.x;
    const int wid = tid >> 5;
    const int lid = tid & 31;
    const int warp_m = wid & 3;        // 4 warps x 32 rows
    const int warp_n = wid >> 2;       // 2 warps x 32 cols

    const int rowBase = blockIdx.y * BM;
    const int colBase = blockIdx.x * BN;

    // per chunk: A 1024 segs + B 512 segs = 1536 x 16B -> 6 cp.async / thread
    auto load_chunk = [&](int kc, int stage) {
        const int k0 = kc * BK;
#pragma unroll
        for (int it = 0; it < 6; it++) {
            const int g = it * 256 + tid;
            if (g < 1024) {
                const int plane = g >> 9;
                const int row   = (g & 511) >> 2;
                const int seg   = g & 3;
                cp_async16(sb + aplane_off(stage, plane) + row * ROWB + seg * 16,
                           Asp + ((size_t)plane * M_DIM + rowBase + row) * K_DIM + k0 + seg * 8);
            } else {
                const int g2    = g - 1024;
                const int plane = g2 >> 8;
                const int row   = (g2 & 255) >> 2;
                const int seg   = g2 & 3;
                cp_async16(sb + bplane_off(stage, plane) + row * ROWB + seg * 16,
                           Bsp + ((size_t)plane * N_DIM + colBase + row) * K_DIM + k0 + seg * 8);
            }
        }
    };

    const int a_row = (lid & 15);
    const int a_ko  = (lid >> 4) * 8;
    const int b_row = (lid & 7) + ((lid >> 4) & 1) * 8;
    const int b_ko  = ((lid >> 3) & 1) * 8;

    // fragments of one k-slab (ks = 0/1): 4 A-ldsm + 2 B-ldsm(x4)
    auto ldsm_slab = [&](int s, int ks, Frag& fr) {
        const int kbyte = ks * 32;
#pragma unroll
        for (int p = 0; p < 2; p++) {
#pragma unroll
            for (int mt = 0; mt < 2; mt++) {
                uint32_t addr = sb + aplane_off(s, p)
                              + (warp_m * 32 + mt * 16 + a_row) * ROWB
                              + kbyte + a_ko * 2;
                ldmx4(fr.af[p][mt], addr);
            }
#pragma unroll
            for (int ng = 0; ng < 2; ng++) {
                uint32_t r[4];
                uint32_t addr = sb + bplane_off(s, p)
                              + (warp_n * 32 + ng * 16 + b_row) * ROWB
                              + kbyte + b_ko * 2;
                ldmx4(r, addr);
                fr.bf[p][ng * 2 + 0][0] = r[0]; fr.bf[p][ng * 2 + 0][1] = r[1];
                fr.bf[p][ng * 2 + 1][0] = r[2]; fr.bf[p][ng * 2 + 1][1] = r[3];
            }
        }
    };

    float acc[2][4][4];                 // 32 regs
#pragma unroll
    for (int mt = 0; mt < 2; mt++)
#pragma unroll
        for (int nt = 0; nt < 4; nt++)
#pragma unroll
            for (int q = 0; q < 4; q++) acc[mt][nt][q] = 0.0f;

    // 24 MMAs per slab: 3 passes x 2 mt x 4 nt
    auto mma_slab = [&](const Frag& fr) {
#pragma unroll
        for (int p = 0; p < 3; p++) {
            const int pa = (p == 2) ? 1 : 0;   // (0,0) (0,1) (1,0)
            const int pb = (p == 1) ? 1 : 0;
#pragma unroll
            for (int mt = 0; mt < 2; mt++)
#pragma unroll
                for (int nt = 0; nt < 4; nt++)
                    mma16816(acc[mt][nt], fr.af[pa][mt], fr.bf[pb][nt]);
        }
    };

    // prologue: chunks 0,1,2 in flight; stage 0 ready; slab (0, ks0) in regs
    load_chunk(0, 0);  CP_COMMIT();
    load_chunk(1, 1);  CP_COMMIT();
    load_chunk(2, 2);  CP_COMMIT();
    CP_WAIT2();
    __syncthreads();

    Frag frag[2];
    ldsm_slab(0, 0, frag[0]);

    for (int i = 0; i < NCHUNK; i++) {
        const int s = i % NSTAGE;

        // prefetch ks=1 fragments of chunk i, then MMA ks=0
        ldsm_slab(s, 1, frag[1]);
        mma_slab(frag[0]);

        // chunk boundary — ALIAS-SAFE ORDER:
        //   wait(chunk i+1 landed) -> barrier (proves all warps done reading
        //   stage s) -> ldsm next chunk ks0 -> only then write stage s
        //   (load_chunk(i+3) aliases stage s under 3-stage rotation).
        if (i + 1 < NCHUNK) {
            if (i + 2 < NCHUNK) { CP_WAIT1(); }   // pending {i+1, i+2}
            else                { CP_WAIT0(); }   // pending {i+1}
            __syncthreads();
            ldsm_slab((i + 1) % NSTAGE, 0, frag[0]);
            if (i + 3 < NCHUNK) {
                load_chunk(i + 3, (i + 3) % NSTAGE);
                CP_COMMIT();
            }
        }

        mma_slab(frag[1]);
    }

    // epilogue
#pragma unroll
    for (int mt = 0; mt < 2; mt++) {
        const int r0 = rowBase + warp_m * 32 + mt * 16 + (lid >> 2);
        const int c0 = colBase + warp_n * 32 + (lid & 3) * 2;
#pragma unroll
        for (int nt = 0; nt < 4; nt++) {
            float* d0 = C + (size_t)r0 * N_DIM + c0 + nt * 8;
            float* d1 = C + (size_t)(r0 + 8) * N_DIM + c0 + nt * 8;
            *(float2*)d0 = make_float2(acc[mt][nt][0], acc[mt][nt][1]);
            *(float2*)d1 = make_float2(acc[mt][nt][2], acc[mt][nt][3]);
        }
    }
}

// ---------------- LIF scan + borderline flagging ----------------
__global__ __launch_bounds__(256)
void lif_flag_kernel(const float* __restrict__ cur, float* __restrict__ out)
{
    const int idx = blockIdx.x * blockDim.x + threadIdx.x;
    float v = 0.0f;
    bool flagged = false;
#pragma unroll
    for (int t = 0; t < T_STEPS; t++) {
        const float x = cur[(size_t)t * S_NEUR + idx];
        const float h = v + (x - v) * 0.5f;
        flagged |= (fabsf(h - 1.0f) < FLAG_EPS);
        const float sp = (h - 1.0f >= 0.0f) ? 1.0f : 0.0f;
        v = (sp != 0.0f) ? 0.0f : h;
        out[(size_t)t * S_NEUR + idx] = sp;
    }
    if (flagged) {
        int p = atomicAdd(&g_flagcnt, 1);
        if (p < MAXF) g_flags[p] = idx;
    }
}

// ---------------- exact fixup: 2 neurons / 128-thread block ----------------
__global__ __launch_bounds__(128)
void fixup_kernel(const float* __restrict__ x, const float* __restrict__ W,
                  float* __restrict__ out)
{
    __shared__ float Wrow[2][K_DIM];
    __shared__ float curex[2][T_STEPS];
    const int count = min(g_flagcnt, MAXF);
    const int sub  = threadIdx.x >> 6;
    const int st   = threadIdx.x & 63;

    for (int base = blockIdx.x * 2; base < count; base += gridDim.x * 2) {
        const int i = base + sub;
        const bool active = (i < count);
        int neuron = 0, b = 0, f = 0;
        if (active) {
            neuron = g_flags[i];
            b = neuron >> 10;
            f = neuron & 1023;
        }
        {
            const float4* wsrc = (const float4*)(W + (size_t)f * K_DIM);
            for (int j = st; j < K_DIM / 4; j += 64)
                ((float4*)Wrow[sub])[j] = wsrc[j];
        }
        __syncthreads();

        if (active) {
            const float4* xr = (const float4*)(x + ((size_t)st * BATCH + b) * K_DIM);
            float acc = 0.0f;
#pragma unroll 4
            for (int kb = 0; kb < K_DIM / 32; kb++) {
                float4 r[8];
#pragma unroll
                for (int q = 0; q < 8; q++) r[q] = xr[kb * 8 + q];
                const float* w = &Wrow[sub][kb * 32];
#pragma unroll
                for (int q = 0; q < 8; q++) {
                    acc = fmaf(r[q].x, w[q * 4 + 0], acc);
                    acc = fmaf(r[q].y, w[q * 4 + 1], acc);
                    acc = fmaf(r[q].z, w[q * 4 + 2], acc);
                    acc = fmaf(r[q].w, w[q * 4 + 3], acc);
                }
            }
            curex[sub][st] = acc;
        }
        __syncthreads();

        if (active && st == 0) {
            float v = 0.0f;
#pragma unroll
            for (int tt = 0; tt < T_STEPS; tt++) {
                const float h = v + (curex[sub][tt] - v) * 0.5f;
                const float sp = (h - 1.0f >= 0.0f) ? 1.0f : 0.0f;
                v = (sp != 0.0f) ? 0.0f : h;
                out[(size_t)tt * S_NEUR + neuron] = sp;
            }
        }
        __syncthreads();
    }
}

// Dummies keep ncu capture (offset-2) on the GEMM:
// pattern [split, d, d, gemm, lif, fixup].
__global__ void align_dummy() {}

// ---------------- launch ----------------
extern "C" void kernel_launch(void* const* d_in, const int* in_sizes, int n_in,
                              void* d_out, int out_size)
{
    (void)in_sizes; (void)n_in; (void)out_size;
    const float* x = (const float*)d_in[0];
    const float* W = (const float*)d_in[1];
    float* out = (float*)d_out;

    float* cur;    cudaGetSymbolAddress((void**)&cur,  g_cur);
    __half* Asp;   cudaGetSymbolAddress((void**)&Asp,  g_Asp);
    __half* Bsp;   cudaGetSymbolAddress((void**)&Bsp,  g_Bsp);

    cudaFuncSetAttribute(gemm_fp16x2,
                         cudaFuncAttributeMaxDynamicSharedMemorySize, SMEM_TOTAL);

    split2_fused<<<SPLIT_A_BLOCKS + SPLIT_B_BLOCKS, 256>>>(x, Asp, W, Bsp);

    align_dummy<<<1, 32>>>();
    align_dummy<<<1, 32>>>();

    dim3 grid(N_DIM / BN, M_DIM / BM);   // (16, 128) = 2048 CTAs
    gemm_fp16x2<<<grid, 256, SMEM_TOTAL>>>(Asp, Bsp, cur);

    lif_flag_kernel<<<S_NEUR / 256, 256>>>(cur, out);

    fixup_kernel<<<1024, 128>>>(x, W, out);
}

// round 13
// speedup vs baseline: 1.2263x; 1.0451x over previous
#include <cuda_runtime.h>
#include <cuda_fp16.h>
#include <cstdint>

// x: [T=64, B=256, F_in=1024] fp32 -> A [M=16384, K=1024]
// W: [F_out=1024, F_in=1024] fp32  -> B [N=1024,  K=1024]
// cur = A @ B^T ; LIF scan over T -> spikes [T, B, F_out] fp32
//
// Approximate-then-repair (validated R6-R12, rel_err 0.0):
//   1) fp16x2 3-pass tensor GEMM (a0b0+a0b1+a1b0), error ~5e-6 rms.
//   2) LIF scan flags neurons with |h-1| < 1.5e-4 (~1.5k of 262k).
//   3) fixup recomputes flagged neurons with the EXACT ascending-k fp32 fmaf
//      chain (bitwise == reference) and reruns their scans.
// R13: fixup regrouped BY BATCH INDEX — one block per b stages the shared
// x[t][b] rows in smem (coalesced, read once chip-wide) instead of ~1500
// neurons each privately streaming the same 256KB. GEMM unchanged.

#define T_STEPS 64
#define BATCH   256
#define K_DIM   1024
#define N_DIM   1024
#define M_DIM   (T_STEPS * BATCH)      // 16384
#define S_NEUR  (BATCH * N_DIM)        // 262144
#define MAXF    65536
#define FLAG_EPS 1.5e-4f

__device__ float   g_cur[(size_t)M_DIM * N_DIM];        // 64 MB
__device__ __half  g_Asp[(size_t)2 * M_DIM * K_DIM];    // 64 MB
__device__ __half  g_Bsp[(size_t)2 * N_DIM * K_DIM];    // 4 MB
__device__ int     g_flags[MAXF];
__device__ int     g_flagcnt;

// ---------------- helpers ----------------
__device__ __forceinline__ uint32_t smem_u32(const void* p) {
    uint32_t a;
    asm("{ .reg .u64 t; cvta.to.shared.u64 t, %1; cvt.u32.u64 %0, t; }"
        : "=r"(a) : "l"(p));
    return a;
}
__device__ __forceinline__ void cp_async16(uint32_t dst, const void* src) {
    asm volatile("cp.async.cg.shared.global [%0], [%1], 16;" :: "r"(dst), "l"(src));
}
#define CP_COMMIT() asm volatile("cp.async.commit_group;" ::: "memory")
#define CP_WAIT0()  asm volatile("cp.async.wait_group 0;" ::: "memory")
#define CP_WAIT1()  asm volatile("cp.async.wait_group 1;" ::: "memory")
#define CP_WAIT2()  asm volatile("cp.async.wait_group 2;" ::: "memory")

__device__ __forceinline__ void ldmx4(uint32_t* r, uint32_t addr) {
    asm volatile("ldmatrix.sync.aligned.m8n8.x4.shared.b16 {%0,%1,%2,%3}, [%4];"
                 : "=r"(r[0]), "=r"(r[1]), "=r"(r[2]), "=r"(r[3]) : "r"(addr));
}
__device__ __forceinline__ void mma16816(float* c, const uint32_t* a, const uint32_t* b) {
    asm volatile(
        "mma.sync.aligned.m16n8k16.row.col.f32.f16.f16.f32 "
        "{%0,%1,%2,%3}, {%4,%5,%6,%7}, {%8,%9}, {%0,%1,%2,%3};"
        : "+f"(c[0]), "+f"(c[1]), "+f"(c[2]), "+f"(c[3])
        : "r"(a[0]), "r"(a[1]), "r"(a[2]), "r"(a[3]), "r"(b[0]), "r"(b[1]));
}

// ---------------- split2 precompute (fp16 two-way split) ----------------
#define SPLIT_A_BLOCKS ((M_DIM * K_DIM) / 4 / 256)   // 16384
#define SPLIT_B_BLOCKS ((N_DIM * K_DIM) / 4 / 256)   // 1024

__global__ __launch_bounds__(256)
void split2_fused(const float* __restrict__ inA, __half* __restrict__ outA,
                  const float* __restrict__ inB, __half* __restrict__ outB)
{
    if (blockIdx.x == 0 && threadIdx.x == 0) g_flagcnt = 0;
    const float* in;
    __half* out;
    size_t n, idx;
    if (blockIdx.x < SPLIT_A_BLOCKS) {
        in = inA; out = outA; n = (size_t)M_DIM * K_DIM;
        idx = ((size_t)blockIdx.x * 256 + threadIdx.x) * 4;
    } else {
        in = inB; out = outB; n = (size_t)N_DIM * K_DIM;
        idx = ((size_t)(blockIdx.x - SPLIT_A_BLOCKS) * 256 + threadIdx.x) * 4;
    }
    float4 v = *(const float4*)(in + idx);
    __half h0[4], h1[4];
    h0[0] = __float2half_rn(v.x); h1[0] = __float2half_rn(v.x - __half2float(h0[0]));
    h0[1] = __float2half_rn(v.y); h1[1] = __float2half_rn(v.y - __half2float(h0[1]));
    h0[2] = __float2half_rn(v.z); h1[2] = __float2half_rn(v.z - __half2float(h0[2]));
    h0[3] = __float2half_rn(v.w); h1[3] = __float2half_rn(v.w - __half2float(h0[3]));
    __half2* o0 = (__half2*)(out + idx);
    __half2* o1 = (__half2*)(out + n + idx);
    o0[0] = __halves2half2(h0[0], h0[1]);  o0[1] = __halves2half2(h0[2], h0[3]);
    o1[0] = __halves2half2(h1[0], h1[1]);  o1[1] = __halves2half2(h1[2], h1[3]);
}

// ------- fp16x2 3-pass GEMM, 128x64 tile, 3 stages, 2 CTAs/SM (R12, proven) -------
#define BM 128
#define BN 64
#define BK 32
#define NCHUNK (K_DIM / BK)            // 32
#define ROWB 80
#define A_PLANE_B (128 * ROWB)         // 10240
#define B_PLANE_B (64 * ROWB)          // 5120
#define STAGE_B (2 * A_PLANE_B + 2 * B_PLANE_B)   // 30720
#define NSTAGE 3
#define SMEM_TOTAL (NSTAGE * STAGE_B)  // 92160

__device__ __forceinline__ uint32_t aplane_off(int stage, int plane) {
    return stage * STAGE_B + plane * A_PLANE_B;
}
__device__ __forceinline__ uint32_t bplane_off(int stage, int plane) {
    return stage * STAGE_B + 2 * A_PLANE_B + plane * B_PLANE_B;
}

struct Frag {
    uint32_t af[2][2][4];
    uint32_t bf[2][4][2];
};

__global__ __launch_bounds__(256, 2)
void gemm_fp16x2(const __half* __restrict__ Asp,
                 const __half* __restrict__ Bsp,
                 float* __restrict__ C)
{
    extern __shared__ char smem[];
    const uint32_t sb = smem_u32(smem);
    const int tid = threadIdx.x;
    const int wid = tid >> 5;
    const int lid = tid & 31;
    const int warp_m = wid & 3;
    const int warp_n = wid >> 2;

    const int rowBase = blockIdx.y * BM;
    const int colBase = blockIdx.x * BN;

    auto load_chunk = [&](int kc, int stage) {
        const int k0 = kc * BK;
#pragma unroll
        for (int it = 0; it < 6; it++) {
            const int g = it * 256 + tid;
            if (g < 1024) {
                const int plane = g >> 9;
                const int row   = (g & 511) >> 2;
                const int seg   = g & 3;
                cp_async16(sb + aplane_off(stage, plane) + row * ROWB + seg * 16,
                           Asp + ((size_t)plane * M_DIM + rowBase + row) * K_DIM + k0 + seg * 8);
            } else {
                const int g2    = g - 1024;
                const int plane = g2 >> 8;
                const int row   = (g2 & 255) >> 2;
                const int seg   = g2 & 3;
                cp_async16(sb + bplane_off(stage, plane) + row * ROWB + seg * 16,
                           Bsp + ((size_t)plane * N_DIM + colBase + row) * K_DIM + k0 + seg * 8);
            }
        }
    };

    const int a_row = (lid & 15);
    const int a_ko  = (lid >> 4) * 8;
    const int b_row = (lid & 7) + ((lid >> 4) & 1) * 8;
    const int b_ko  = ((lid >> 3) & 1) * 8;

    auto ldsm_slab = [&](int s, int ks, Frag& fr) {
        const int kbyte = ks * 32;
#pragma unroll
        for (int p = 0; p < 2; p++) {
#pragma unroll
            for (int mt = 0; mt < 2; mt++) {
                uint32_t addr = sb + aplane_off(s, p)
                              + (warp_m * 32 + mt * 16 + a_row) * ROWB
                              + kbyte + a_ko * 2;
                ldmx4(fr.af[p][mt], addr);
            }
#pragma unroll
            for (int ng = 0; ng < 2; ng++) {
                uint32_t r[4];
                uint32_t addr = sb + bplane_off(s, p)
                              + (warp_n * 32 + ng * 16 + b_row) * ROWB
                              + kbyte + b_ko * 2;
                ldmx4(r, addr);
                fr.bf[p][ng * 2 + 0][0] = r[0]; fr.bf[p][ng * 2 + 0][1] = r[1];
                fr.bf[p][ng * 2 + 1][0] = r[2]; fr.bf[p][ng * 2 + 1][1] = r[3];
            }
        }
    };

    float acc[2][4][4];
#pragma unroll
    for (int mt = 0; mt < 2; mt++)
#pragma unroll
        for (int nt = 0; nt < 4; nt++)
#pragma unroll
            for (int q = 0; q < 4; q++) acc[mt][nt][q] = 0.0f;

    auto mma_slab = [&](const Frag& fr) {
#pragma unroll
        for (int p = 0; p < 3; p++) {
            const int pa = (p == 2) ? 1 : 0;
            const int pb = (p == 1) ? 1 : 0;
#pragma unroll
            for (int mt = 0; mt < 2; mt++)
#pragma unroll
                for (int nt = 0; nt < 4; nt++)
                    mma16816(acc[mt][nt], fr.af[pa][mt], fr.bf[pb][nt]);
        }
    };

    load_chunk(0, 0);  CP_COMMIT();
    load_chunk(1, 1);  CP_COMMIT();
    load_chunk(2, 2);  CP_COMMIT();
    CP_WAIT2();
    __syncthreads();

    Frag frag[2];
    ldsm_slab(0, 0, frag[0]);

    for (int i = 0; i < NCHUNK; i++) {
        const int s = i % NSTAGE;

        ldsm_slab(s, 1, frag[1]);
        mma_slab(frag[0]);

        if (i + 1 < NCHUNK) {
            if (i + 2 < NCHUNK) { CP_WAIT1(); }
            else                { CP_WAIT0(); }
            __syncthreads();
            ldsm_slab((i + 1) % NSTAGE, 0, frag[0]);
            if (i + 3 < NCHUNK) {
                load_chunk(i + 3, (i + 3) % NSTAGE);
                CP_COMMIT();
            }
        }

        mma_slab(frag[1]);
    }

#pragma unroll
    for (int mt = 0; mt < 2; mt++) {
        const int r0 = rowBase + warp_m * 32 + mt * 16 + (lid >> 2);
        const int c0 = colBase + warp_n * 32 + (lid & 3) * 2;
#pragma unroll
        for (int nt = 0; nt < 4; nt++) {
            float* d0 = C + (size_t)r0 * N_DIM + c0 + nt * 8;
            float* d1 = C + (size_t)(r0 + 8) * N_DIM + c0 + nt * 8;
            *(float2*)d0 = make_float2(acc[mt][nt][0], acc[mt][nt][1]);
            *(float2*)d1 = make_float2(acc[mt][nt][2], acc[mt][nt][3]);
        }
    }
}

// ---------------- LIF scan + borderline flagging ----------------
__global__ __launch_bounds__(256)
void lif_flag_kernel(const float* __restrict__ cur, float* __restrict__ out)
{
    const int idx = blockIdx.x * blockDim.x + threadIdx.x;
    float v = 0.0f;
    bool flagged = false;
#pragma unroll
    for (int t = 0; t < T_STEPS; t++) {
        const float x = cur[(size_t)t * S_NEUR + idx];
        const float h = v + (x - v) * 0.5f;
        flagged |= (fabsf(h - 1.0f) < FLAG_EPS);
        const float sp = (h - 1.0f >= 0.0f) ? 1.0f : 0.0f;
        v = (sp != 0.0f) ? 0.0f : h;
        out[(size_t)t * S_NEUR + idx] = sp;
    }
    if (flagged) {
        int p = atomicAdd(&g_flagcnt, 1);
        if (p < MAXF) g_flags[p] = idx;
    }
}

// ------------- exact fixup, grouped by batch index b (R13) -------------
// One block per b. Stages x[t][b] k-tiles in smem (shared by ALL flagged
// neurons of that b: x read once chip-wide) + W rows of the flagged f's.
// Thread (t, j) runs the exact ascending-k fp32 fmaf chain (bitwise ==
// reference), then one thread per f reruns the LIF scan.
#define FL_CAP 256
#define WG 8                            // W rows staged per pass
__global__ __launch_bounds__(256)
void fixup_kernel(const float* __restrict__ x, const float* __restrict__ W,
                  float* __restrict__ out)
{
    __shared__ float xs[64 * 129];      // [t][k] rows padded to 129 (conflict-free)
    __shared__ float ws[WG][128];
    __shared__ float cx[WG][T_STEPS];
    __shared__ int   fl[FL_CAP];
    __shared__ int   nf_s;

    const int b   = blockIdx.x;         // 0..255
    const int tid = threadIdx.x;

    if (tid == 0) nf_s = 0;
    __syncthreads();

    // gather this b's flagged features
    const int count = min(g_flagcnt, MAXF);
    for (int i = tid; i < count; i += 256) {
        const int neuron = g_flags[i];
        if ((neuron >> 10) == b) {
            int p = atomicAdd(&nf_s, 1);
            if (p < FL_CAP) fl[p] = neuron & 1023;
        }
    }
    __syncthreads();
    const int nf = min(nf_s, FL_CAP);
    if (nf == 0) return;

    const int t = tid & 63;             // timestep owned by this thread
    const int j = tid >> 6;             // 0..3 (f slots j and j+4)

    for (int f0 = 0; f0 < nf; f0 += WG) {
        const int ng = min(WG, nf - f0);
        float acc0 = 0.0f, acc1 = 0.0f;

        for (int k0 = 0; k0 < K_DIM; k0 += 128) {
            // stage x[t][b][k0:k0+128] for all 64 t (coalesced float4 loads)
            for (int q = tid; q < 64 * 32; q += 256) {
                const int tt = q >> 5;
                const int k4 = q & 31;
                float4 v = *(const float4*)(x + ((size_t)tt * BATCH + b) * K_DIM + k0 + k4 * 4);
                float* dst = &xs[tt * 129 + k4 * 4];
                dst[0] = v.x; dst[1] = v.y; dst[2] = v.z; dst[3] = v.w;
            }
            // stage W rows
            if (tid < ng * 32) {
                const int jj = tid >> 5;
                const int k4 = tid & 31;
                *(float4*)&ws[jj][k4 * 4] =
                    *(const float4*)(W + (size_t)fl[f0 + jj] * K_DIM + k0 + k4 * 4);
            }
            __syncthreads();

            const float* xrow = &xs[t * 129];
            if (j < ng) {
                const float* w = ws[j];
#pragma unroll 8
                for (int k = 0; k < 128; k++)
                    acc0 = fmaf(xrow[k], w[k], acc0);
            }
            if (j + 4 < ng) {
                const float* w = ws[j + 4];
#pragma unroll 8
                for (int k = 0; k < 128; k++)
                    acc1 = fmaf(xrow[k], w[k], acc1);
            }
            __syncthreads();
        }

        if (j < ng)     cx[j][t]     = acc0;
        if (j + 4 < ng) cx[j + 4][t] = acc1;
        __syncthreads();

        // per-f exact LIF rescan
        if (tid < ng) {
            const int neuron = (b << 10) | fl[f0 + tid];
            float v = 0.0f;
#pragma unroll
            for (int tt = 0; tt < T_STEPS; tt++) {
                const float h = v + (cx[tid][tt] - v) * 0.5f;
                const float sp = (h - 1.0f >= 0.0f) ? 1.0f : 0.0f;
                v = (sp != 0.0f) ? 0.0f : h;
                out[(size_t)tt * S_NEUR + neuron] = sp;
            }
        }
        __syncthreads();
    }
}

// ---------------- launch ----------------
// Pattern [split, gemm, lif, fixup]: capture rule pattern[(5-2) mod 4] = 3
// -> ncu profiles the NEW fixup this round.
extern "C" void kernel_launch(void* const* d_in, const int* in_sizes, int n_in,
                              void* d_out, int out_size)
{
    (void)in_sizes; (void)n_in; (void)out_size;
    const float* x = (const float*)d_in[0];
    const float* W = (const float*)d_in[1];
    float* out = (float*)d_out;

    float* cur;    cudaGetSymbolAddress((void**)&cur,  g_cur);
    __half* Asp;   cudaGetSymbolAddress((void**)&Asp,  g_Asp);
    __half* Bsp;   cudaGetSymbolAddress((void**)&Bsp,  g_Bsp);

    cudaFuncSetAttribute(gemm_fp16x2,
                         cudaFuncAttributeMaxDynamicSharedMemorySize, SMEM_TOTAL);

    split2_fused<<<SPLIT_A_BLOCKS + SPLIT_B_BLOCKS, 256>>>(x, Asp, W, Bsp);

    dim3 grid(N_DIM / BN, M_DIM / BM);   // (16, 128) = 2048 CTAs
    gemm_fp16x2<<<grid, 256, SMEM_TOTAL>>>(Asp, Bsp, cur);

    lif_flag_kernel<<<S_NEUR / 256, 256>>>(cur, out);

    fixup_kernel<<<BATCH, 256>>>(x, W, out);
}